// round 3
// baseline (speedup 1.0000x reference)
#include <cuda_runtime.h>
#include <math.h>
#include <stdint.h>

#define NROWS 65536   // B*S = 8*8192
#define EDIM  256
#define NQ    8
#define FDIM  264     // NQ + EDIM

// scratch for quantum layer outputs z[row][q]
__device__ float g_z[(size_t)NROWS * NQ];

// ---------------------------------------------------------------------------
// Kernel A: z = circuit_expvals(x @ W1^T + b1 + qw)
// One warp processes 4 rows. Each lane owns 8 columns (2 float4s), W1 via
// __ldg (8 KB, L1-resident), butterfly reduction, closed-form cos/cumprod.
// ---------------------------------------------------------------------------
__global__ __launch_bounds__(256) void quantum_kernel(
    const float* __restrict__ x, const float* __restrict__ W1,
    const float* __restrict__ b1, const float* __restrict__ qw)
{
    int gwarp = (blockIdx.x * 256 + threadIdx.x) >> 5;
    int lane  = threadIdx.x & 31;
    int row0  = gwarp * 4;
    if (row0 >= NROWS) return;

    const float4* x4 = reinterpret_cast<const float4*>(x);
    float4 xa[4], xb[4];
#pragma unroll
    for (int r = 0; r < 4; r++) {
        const float4* rp = x4 + (size_t)(row0 + r) * (EDIM / 4);
        xa[r] = __ldg(rp + lane);
        xb[r] = __ldg(rp + 32 + lane);
    }

    float acc[4][NQ];
    const float4* w4 = reinterpret_cast<const float4*>(W1);  // [8][64] float4
#pragma unroll
    for (int q = 0; q < NQ; q++) {
        float4 wa = __ldg(w4 + q * 64 + lane);
        float4 wb = __ldg(w4 + q * 64 + 32 + lane);
#pragma unroll
        for (int r = 0; r < 4; r++) {
            float s = xa[r].x * wa.x + xa[r].y * wa.y + xa[r].z * wa.z + xa[r].w * wa.w;
            s      += xb[r].x * wb.x + xb[r].y * wb.y + xb[r].z * wb.z + xb[r].w * wb.w;
            acc[r][q] = s;
        }
    }

#pragma unroll
    for (int r = 0; r < 4; r++)
#pragma unroll
        for (int q = 0; q < NQ; q++)
#pragma unroll
            for (int off = 16; off > 0; off >>= 1)
                acc[r][q] += __shfl_xor_sync(0xffffffffu, acc[r][q], off);

    if (lane < 4) {
        int row = row0 + lane;
        float c[NQ];
#pragma unroll
        for (int q = 0; q < NQ; q++)
            c[q] = cosf(acc[lane][q] + __ldg(b1 + q) + __ldg(qw + q));
        float zv[NQ];
        float s = c[1];
#pragma unroll
        for (int i = 2; i < NQ; i++) s *= c[i];
        zv[0] = s;                       // z0 = prod_{i=1..7} c_i
        float r = c[0];
#pragma unroll
        for (int k = 1; k < NQ; k++) { r *= c[k]; zv[k] = r; }

        float4* zp = reinterpret_cast<float4*>(g_z + (size_t)row * NQ);
        zp[0] = make_float4(zv[0], zv[1], zv[2], zv[3]);
        zp[1] = make_float4(zv[4], zv[5], zv[6], zv[7]);
    }
}

// ---------------------------------------------------------------------------
// Kernel B: out[n,e] = sum_f y[n,f]*W2[e,f] + b2[e],  y = [z | x]
// 128x128x8 fp32 SGEMM, 256 threads, 8x8 micro-tile.
// Double-buffered smem (2-stage ping-pong): exactly ONE __syncthreads per
// K-iteration; next tile's global loads + smem stores overlap this tile's
// 512-FMA compute block.
// K loop: kt=0 reads the z tile (F 0..7), kt>=1 reads x (F 8..263).
// ---------------------------------------------------------------------------
#define BM 128
#define BN 128
#define BK 8
#define KTILES (FDIM / BK)   // 33

__global__ __launch_bounds__(256) void gemm_kernel(
    const float* __restrict__ x, const float* __restrict__ W2,
    const float* __restrict__ b2, float* __restrict__ out)
{
    __shared__ float As[2][BK][BM];
    __shared__ float Bs[2][BK][BN];

    int tid = threadIdx.x;
    int rowBase = blockIdx.x * BM;
    int colBase = blockIdx.y * BN;

    int lr = tid >> 1;          // 0..127 : tile row loaded by this thread
    int lc = (tid & 1) * 4;     // 0 or 4 : K-offset of the float4 it loads
    int tr = (tid >> 4) * 8;    // micro-tile row origin
    int tc = (tid & 15) * 8;    // micro-tile col origin

    float acc[8][8];
#pragma unroll
    for (int i = 0; i < 8; i++)
#pragma unroll
        for (int j = 0; j < 8; j++) acc[i][j] = 0.f;

    const float* Az = g_z + (size_t)(rowBase + lr) * NQ + lc;
    const float* Ax = x   + (size_t)(rowBase + lr) * EDIM + lc;
    const float* Bw = W2  + (size_t)(colBase + lr) * FDIM + lc;

    // prologue: tile 0 (the z tile) into buffer 0
    {
        float4 av = *reinterpret_cast<const float4*>(Az);
        float4 bv = *reinterpret_cast<const float4*>(Bw);
        As[0][lc + 0][lr] = av.x; As[0][lc + 1][lr] = av.y;
        As[0][lc + 2][lr] = av.z; As[0][lc + 3][lr] = av.w;
        Bs[0][lc + 0][lr] = bv.x; Bs[0][lc + 1][lr] = bv.y;
        Bs[0][lc + 2][lr] = bv.z; Bs[0][lc + 3][lr] = bv.w;
    }
    __syncthreads();

    for (int kt = 0; kt < KTILES; kt++) {
        int cur = kt & 1;
        int nxt = cur ^ 1;

        float4 av, bv;
        bool has_next = (kt + 1 < KTILES);
        if (has_next) {
            av = *reinterpret_cast<const float4*>(Ax + kt * BK);       // tile kt+1 = x block kt
            bv = *reinterpret_cast<const float4*>(Bw + (kt + 1) * BK);
        }

#pragma unroll
        for (int k = 0; k < BK; k++) {
            float a[8], b[8];
            *reinterpret_cast<float4*>(a)     = *reinterpret_cast<const float4*>(&As[cur][k][tr]);
            *reinterpret_cast<float4*>(a + 4) = *reinterpret_cast<const float4*>(&As[cur][k][tr + 4]);
            *reinterpret_cast<float4*>(b)     = *reinterpret_cast<const float4*>(&Bs[cur][k][tc]);
            *reinterpret_cast<float4*>(b + 4) = *reinterpret_cast<const float4*>(&Bs[cur][k][tc + 4]);
#pragma unroll
            for (int i = 0; i < 8; i++)
#pragma unroll
                for (int j = 0; j < 8; j++)
                    acc[i][j] += a[i] * b[j];
        }

        if (has_next) {
            As[nxt][lc + 0][lr] = av.x; As[nxt][lc + 1][lr] = av.y;
            As[nxt][lc + 2][lr] = av.z; As[nxt][lc + 3][lr] = av.w;
            Bs[nxt][lc + 0][lr] = bv.x; Bs[nxt][lc + 1][lr] = bv.y;
            Bs[nxt][lc + 2][lr] = bv.z; Bs[nxt][lc + 3][lr] = bv.w;
            __syncthreads();
        }
    }

    float4 bb0 = *reinterpret_cast<const float4*>(b2 + colBase + tc);
    float4 bb1 = *reinterpret_cast<const float4*>(b2 + colBase + tc + 4);
#pragma unroll
    for (int i = 0; i < 8; i++) {
        float* op = out + (size_t)(rowBase + tr + i) * EDIM + colBase + tc;
        float4 v0 = make_float4(acc[i][0] + bb0.x, acc[i][1] + bb0.y,
                                acc[i][2] + bb0.z, acc[i][3] + bb0.w);
        float4 v1 = make_float4(acc[i][4] + bb1.x, acc[i][5] + bb1.y,
                                acc[i][6] + bb1.z, acc[i][7] + bb1.w);
        *reinterpret_cast<float4*>(op)     = v0;
        *reinterpret_cast<float4*>(op + 4) = v1;
    }
}

// ---------------------------------------------------------------------------
extern "C" void kernel_launch(void* const* d_in, const int* in_sizes, int n_in,
                              void* d_out, int out_size) {
    const float* x  = (const float*)d_in[0];
    const float* W1 = (const float*)d_in[1];
    const float* b1 = (const float*)d_in[2];
    const float* qw = (const float*)d_in[3];
    const float* W2 = (const float*)d_in[4];
    const float* b2 = (const float*)d_in[5];
    float* out = (float*)d_out;

    quantum_kernel<<<NROWS / 32, 256>>>(x, W1, b1, qw);

    dim3 grid(NROWS / BM, EDIM / BN);
    gemm_kernel<<<grid, 256>>>(x, W2, b2, out);
}

// round 6
// speedup vs baseline: 1.9049x; 1.9049x over previous
#include <cuda_runtime.h>
#include <math.h>
#include <stdint.h>

#define NROWS 65536   // B*S = 8*8192
#define EDIM  256
#define NQ    8
#define FDIM  264     // NQ + EDIM

// scratch for quantum layer outputs z[row][q]
__device__ float g_z[(size_t)NROWS * NQ];

// ---------------------------------------------------------------------------
// Kernel A: z = circuit_expvals(x @ W1^T + b1 + qw)
// One warp processes 8 rows (front-batched: 16 LDG.128 per lane for MLP).
// W1 via __ldg (8 KB, L1-resident), butterfly reduce, closed-form cos/cumprod.
// ---------------------------------------------------------------------------
__global__ __launch_bounds__(256) void quantum_kernel(
    const float* __restrict__ x, const float* __restrict__ W1,
    const float* __restrict__ b1, const float* __restrict__ qw)
{
    int gwarp = (blockIdx.x * 256 + threadIdx.x) >> 5;
    int lane  = threadIdx.x & 31;
    int row0  = gwarp * 8;
    if (row0 >= NROWS) return;

    const float4* x4 = reinterpret_cast<const float4*>(x);
    float4 xa[8], xb[8];
#pragma unroll
    for (int r = 0; r < 8; r++) {
        const float4* rp = x4 + (size_t)(row0 + r) * (EDIM / 4);
        xa[r] = __ldg(rp + lane);
        xb[r] = __ldg(rp + 32 + lane);
    }

    float acc[8][NQ];
    const float4* w4 = reinterpret_cast<const float4*>(W1);  // [8][64] float4
#pragma unroll
    for (int q = 0; q < NQ; q++) {
        float4 wa = __ldg(w4 + q * 64 + lane);
        float4 wb = __ldg(w4 + q * 64 + 32 + lane);
#pragma unroll
        for (int r = 0; r < 8; r++) {
            float s = xa[r].x * wa.x + xa[r].y * wa.y + xa[r].z * wa.z + xa[r].w * wa.w;
            s      += xb[r].x * wb.x + xb[r].y * wb.y + xb[r].z * wb.z + xb[r].w * wb.w;
            acc[r][q] = s;
        }
    }

#pragma unroll
    for (int r = 0; r < 8; r++)
#pragma unroll
        for (int q = 0; q < NQ; q++)
#pragma unroll
            for (int off = 16; off > 0; off >>= 1)
                acc[r][q] += __shfl_xor_sync(0xffffffffu, acc[r][q], off);

    if (lane < 8) {
        int row = row0 + lane;
        float c[NQ];
#pragma unroll
        for (int q = 0; q < NQ; q++)
            c[q] = cosf(acc[lane][q] + __ldg(b1 + q) + __ldg(qw + q));
        float zv[NQ];
        float s = c[1];
#pragma unroll
        for (int i = 2; i < NQ; i++) s *= c[i];
        zv[0] = s;                       // z0 = prod_{i=1..7} c_i
        float r = c[0];
#pragma unroll
        for (int k = 1; k < NQ; k++) { r *= c[k]; zv[k] = r; }

        float4* zp = reinterpret_cast<float4*>(g_z + (size_t)row * NQ);
        zp[0] = make_float4(zv[0], zv[1], zv[2], zv[3]);
        zp[1] = make_float4(zv[4], zv[5], zv[6], zv[7]);
    }
}

// ---------------------------------------------------------------------------
// Kernel B: out[n,e] = sum_f y[n,f]*W2[e,f] + b2[e],  y = [z | x]
// Tensor-core tf32 mma.sync.m16n8k8. CTA tile 128x128, 8 warps (2x4),
// warp tile 64x32 = 4x4 atoms of m16n8. K-tiles of 8, 33 steps.
// Smem stride-12 padding -> conflict-free fragment LDS (12g+q distinct mod 32).
// Double-buffered smem, register prefetch, one __syncthreads per K-iter.
// ---------------------------------------------------------------------------
#define BM 128
#define BN 128
#define BK 8
#define PADK 12
#define KTILES (FDIM / BK)   // 33

// tf32 is a b32-typed value in PTX: destination must be a .b32 register.
__device__ __forceinline__ uint32_t to_tf32(float v) {
    uint32_t r;
    asm("cvt.rna.tf32.f32 %0, %1;" : "=r"(r) : "f"(v));
    return r;
}
__device__ __forceinline__ float to_tf32f(float v) {
    return __uint_as_float(to_tf32(v));
}

__device__ __forceinline__ void mma_tf32(float* d, const uint32_t* a, const uint32_t* b) {
    asm volatile(
        "mma.sync.aligned.m16n8k8.row.col.f32.tf32.tf32.f32 "
        "{%0,%1,%2,%3},{%4,%5,%6,%7},{%8,%9},{%0,%1,%2,%3};"
        : "+f"(d[0]), "+f"(d[1]), "+f"(d[2]), "+f"(d[3])
        : "r"(a[0]), "r"(a[1]), "r"(a[2]), "r"(a[3]), "r"(b[0]), "r"(b[1]));
}

__global__ __launch_bounds__(256) void gemm_kernel(
    const float* __restrict__ x, const float* __restrict__ W2,
    const float* __restrict__ b2, float* __restrict__ out)
{
    __shared__ float As[2][BM][PADK];   // [row m][k]
    __shared__ float Bs[2][BN][PADK];   // [col n][k]

    int tid  = threadIdx.x;
    int wid  = tid >> 5;
    int lane = tid & 31;
    int g    = lane >> 2;   // 0..7
    int q    = lane & 3;    // 0..3

    int warp_m = (wid & 1) * 64;   // 0 or 64
    int warp_n = (wid >> 1) * 32;  // 0,32,64,96

    int rowBase = blockIdx.x * BM;
    int colBase = blockIdx.y * BN;

    // loader mapping: 256 threads, one float4 each for A and B per K-tile
    int lr = tid >> 1;          // 0..127
    int lc = (tid & 1) * 4;     // 0 or 4

    const float* Az = g_z + (size_t)(rowBase + lr) * NQ + lc;
    const float* Ax = x   + (size_t)(rowBase + lr) * EDIM + lc;
    const float* Bw = W2  + (size_t)(colBase + lr) * FDIM + lc;

    float acc[4][4][4];
#pragma unroll
    for (int i = 0; i < 4; i++)
#pragma unroll
        for (int j = 0; j < 4; j++)
#pragma unroll
            for (int v = 0; v < 4; v++) acc[i][j][v] = 0.f;

    // prologue: tile 0 (the z tile) into buffer 0
    {
        float4 av = *reinterpret_cast<const float4*>(Az);
        float4 bv = *reinterpret_cast<const float4*>(Bw);
        As[0][lr][lc + 0] = to_tf32f(av.x); As[0][lr][lc + 1] = to_tf32f(av.y);
        As[0][lr][lc + 2] = to_tf32f(av.z); As[0][lr][lc + 3] = to_tf32f(av.w);
        Bs[0][lr][lc + 0] = to_tf32f(bv.x); Bs[0][lr][lc + 1] = to_tf32f(bv.y);
        Bs[0][lr][lc + 2] = to_tf32f(bv.z); Bs[0][lr][lc + 3] = to_tf32f(bv.w);
    }
    __syncthreads();

    for (int kt = 0; kt < KTILES; kt++) {
        int cur = kt & 1;
        int nxt = cur ^ 1;
        bool has_next = (kt + 1 < KTILES);

        float4 av, bv;
        if (has_next) {
            av = *reinterpret_cast<const float4*>(Ax + kt * BK);       // tile kt+1 = x block kt
            bv = *reinterpret_cast<const float4*>(Bw + (kt + 1) * BK);
        }

        // fragment loads (conflict-free via PADK=12)
        uint32_t afr[4][4], bfr[4][2];
#pragma unroll
        for (int ma = 0; ma < 4; ma++) {
            int r0 = warp_m + ma * 16 + g;
            afr[ma][0] = __float_as_uint(As[cur][r0    ][q    ]);
            afr[ma][1] = __float_as_uint(As[cur][r0 + 8][q    ]);
            afr[ma][2] = __float_as_uint(As[cur][r0    ][q + 4]);
            afr[ma][3] = __float_as_uint(As[cur][r0 + 8][q + 4]);
        }
#pragma unroll
        for (int nb = 0; nb < 4; nb++) {
            int c0 = warp_n + nb * 8 + g;
            bfr[nb][0] = __float_as_uint(Bs[cur][c0][q    ]);
            bfr[nb][1] = __float_as_uint(Bs[cur][c0][q + 4]);
        }

#pragma unroll
        for (int ma = 0; ma < 4; ma++)
#pragma unroll
            for (int nb = 0; nb < 4; nb++)
                mma_tf32(acc[ma][nb], afr[ma], bfr[nb]);

        if (has_next) {
            As[nxt][lr][lc + 0] = to_tf32f(av.x); As[nxt][lr][lc + 1] = to_tf32f(av.y);
            As[nxt][lr][lc + 2] = to_tf32f(av.z); As[nxt][lr][lc + 3] = to_tf32f(av.w);
            Bs[nxt][lr][lc + 0] = to_tf32f(bv.x); Bs[nxt][lr][lc + 1] = to_tf32f(bv.y);
            Bs[nxt][lr][lc + 2] = to_tf32f(bv.z); Bs[nxt][lr][lc + 3] = to_tf32f(bv.w);
            __syncthreads();
        }
    }

    // epilogue: bias + store. c0,c1 at (g, 2q..2q+1); c2,c3 at (g+8, ...)
#pragma unroll
    for (int ma = 0; ma < 4; ma++) {
#pragma unroll
        for (int nb = 0; nb < 4; nb++) {
            int col  = colBase + warp_n + nb * 8 + 2 * q;
            int row0 = rowBase + warp_m + ma * 16 + g;
            float bias0 = __ldg(b2 + col);
            float bias1 = __ldg(b2 + col + 1);
            float2 v0 = make_float2(acc[ma][nb][0] + bias0, acc[ma][nb][1] + bias1);
            float2 v1 = make_float2(acc[ma][nb][2] + bias0, acc[ma][nb][3] + bias1);
            *reinterpret_cast<float2*>(out + (size_t)row0 * EDIM + col)       = v0;
            *reinterpret_cast<float2*>(out + (size_t)(row0 + 8) * EDIM + col) = v1;
        }
    }
}

// ---------------------------------------------------------------------------
extern "C" void kernel_launch(void* const* d_in, const int* in_sizes, int n_in,
                              void* d_out, int out_size) {
    const float* x  = (const float*)d_in[0];
    const float* W1 = (const float*)d_in[1];
    const float* b1 = (const float*)d_in[2];
    const float* qw = (const float*)d_in[3];
    const float* W2 = (const float*)d_in[4];
    const float* b2 = (const float*)d_in[5];
    float* out = (float*)d_out;

    // Kernel A: 8 warps/block * 8 rows/warp = 64 rows per block
    quantum_kernel<<<NROWS / 64, 256>>>(x, W1, b1, qw);

    dim3 grid(NROWS / BM, EDIM / BN);
    gemm_kernel<<<grid, 256>>>(x, W2, b2, out);
}